// round 5
// baseline (speedup 1.0000x reference)
#include <cuda_runtime.h>
#include <cuda_bf16.h>
#include <cstdint>

// BiATT algebraic collapse: softmax over axis=1 of a [N,1] tensor == 1.0, so
// all four bi-attention branches are identity. cf = atoms @ (sum Wcc blocks) + bcc,
// pf = amino @ (sum Wcp blocks) + bcp  =>  two [6144x512]@[512x512] fp32 GEMMs.
// 3-way bf16 split  A@W ~= Ah@Wh + Al@Wh + Ah@Wl, fp32 accum, mma.sync m16n8k16.
// R5: A split precomputed to global bf16; GEMM mainloop is pure cp.async
// double-buffered bf16 tile streaming (no fp32 LDG / convert in hot loop).

#define DIM     512
#define M_ROWS  6144
#define BM      128
#define BN      128
#define BK      32
#define NCHUNK  (DIM / BK)     // 16

// preformed bf16 operands
__device__ __nv_bfloat16 g_Wh[2][DIM * DIM];   // folded, transposed [N][K]
__device__ __nv_bfloat16 g_Wl[2][DIM * DIM];
__device__ __nv_bfloat16 g_Ah[2][M_ROWS * DIM];
__device__ __nv_bfloat16 g_Al[2][M_ROWS * DIM];

// ---- smem: rows of 32 bf16 padded to 80 B (conflict-free ldmatrix), x2 buffers
#define PITCH    80
#define STAGE    (4 * BM * PITCH)        // AH+AL+BH+BL = 40960 per stage
#define SM_AH    0
#define SM_AL    (BM * PITCH)
#define SM_BH    (2 * BM * PITCH)
#define SM_BL    (3 * BM * PITCH)
#define SM_BIAS  (2 * STAGE)             // 81920
#define SM_TOT   (SM_BIAS + 512)         // 82432 dynamic

// ---------------------------------------------------------------- helpers
__device__ __forceinline__ uint32_t smem_u32(const void* p) {
    return (uint32_t)__cvta_generic_to_shared(p);
}
__device__ __forceinline__ uint32_t pack_bf2(__nv_bfloat16 a, __nv_bfloat16 b) {
    __nv_bfloat162 t(a, b);
    return *reinterpret_cast<uint32_t*>(&t);
}
__device__ __forceinline__ void cp16(uint32_t dst, const void* src) {
    asm volatile("cp.async.cg.shared.global [%0], [%1], 16;"
                 :: "r"(dst), "l"(src));
}
__device__ __forceinline__ void cp_commit() {
    asm volatile("cp.async.commit_group;");
}
__device__ __forceinline__ void cp_wait0() {
    asm volatile("cp.async.wait_group 0;");
}
__device__ __forceinline__ void ldsm_x4(uint32_t* r, uint32_t addr) {
    asm volatile("ldmatrix.sync.aligned.m8n8.x4.shared.b16 {%0,%1,%2,%3}, [%4];"
                 : "=r"(r[0]), "=r"(r[1]), "=r"(r[2]), "=r"(r[3]) : "r"(addr));
}
__device__ __forceinline__ void mma_bf16(float* d, const uint32_t* a,
                                         uint32_t b0, uint32_t b1) {
    asm volatile(
        "mma.sync.aligned.m16n8k16.row.col.f32.bf16.bf16.f32 "
        "{%0,%1,%2,%3}, {%4,%5,%6,%7}, {%8,%9}, {%0,%1,%2,%3};"
        : "+f"(d[0]), "+f"(d[1]), "+f"(d[2]), "+f"(d[3])
        : "r"(a[0]), "r"(a[1]), "r"(a[2]), "r"(a[3]), "r"(b0), "r"(b1));
}

// ----------------------------------------------- prologue 1: fold + T + split W
// g_Wh/g_Wl[z][n*512+k] = bf16 hi/lo of sum_b Wsrc[(b*512+k)*512+n]
__global__ void fold_split_kernel(const float* __restrict__ Wcc,
                                  const float* __restrict__ Wcp) {
    __shared__ float s[32][33];
    const int z = blockIdx.z;
    const float* __restrict__ W = z ? Wcp : Wcc;
    const int k = blockIdx.y * 32 + threadIdx.y;
    const int n = blockIdx.x * 32 + threadIdx.x;
    float v = 0.f;
#pragma unroll
    for (int b = 0; b < 4; b++) v += W[(size_t)(b * DIM + k) * DIM + n];
    s[threadIdx.y][threadIdx.x] = v;
    __syncthreads();
    const int n2 = blockIdx.x * 32 + threadIdx.y;
    const int k2 = blockIdx.y * 32 + threadIdx.x;
    const float val = s[threadIdx.x][threadIdx.y];
    __nv_bfloat16 h = __float2bfloat16(val);
    __nv_bfloat16 l = __float2bfloat16(val - __bfloat162float(h));
    g_Wh[z][(size_t)n2 * DIM + k2] = h;
    g_Wl[z][(size_t)n2 * DIM + k2] = l;
}

// ----------------------------------------------- prologue 2: split A to bf16
__global__ void __launch_bounds__(256)
split_A_kernel(const float* __restrict__ atoms, const float* __restrict__ amino) {
    const int z = blockIdx.y;
    const float* __restrict__ X = z ? amino : atoms;
    const size_t idx = ((size_t)blockIdx.x * 256 + threadIdx.x) * 4;
    float4 v = *reinterpret_cast<const float4*>(&X[idx]);
    __nv_bfloat16 h0 = __float2bfloat16(v.x);
    __nv_bfloat16 h1 = __float2bfloat16(v.y);
    __nv_bfloat16 h2 = __float2bfloat16(v.z);
    __nv_bfloat16 h3 = __float2bfloat16(v.w);
    __nv_bfloat16 l0 = __float2bfloat16(v.x - __bfloat162float(h0));
    __nv_bfloat16 l1 = __float2bfloat16(v.y - __bfloat162float(h1));
    __nv_bfloat16 l2 = __float2bfloat16(v.z - __bfloat162float(h2));
    __nv_bfloat16 l3 = __float2bfloat16(v.w - __bfloat162float(h3));
    uint2 hi = make_uint2(pack_bf2(h0, h1), pack_bf2(h2, h3));
    uint2 lo = make_uint2(pack_bf2(l0, l1), pack_bf2(l2, l3));
    *reinterpret_cast<uint2*>(&g_Ah[z][idx]) = hi;
    *reinterpret_cast<uint2*>(&g_Al[z][idx]) = lo;
}

// --------------------------------------------------- HMMA GEMM + bias
// grid (4, 48, 2), 256 threads; warp tile 64x32 (2x4 warp grid); 2-stage pipe
__global__ void __launch_bounds__(256, 2)
biatt_gemm_kernel(const float* __restrict__ bcc,
                  const float* __restrict__ bcp,
                  float* __restrict__ out) {
    extern __shared__ __align__(16) char sm[];
    const uint32_t sbase = smem_u32(sm);

    const int tid  = threadIdx.x;
    const int wid  = tid >> 5;
    const int lane = tid & 31;
    const int z    = blockIdx.z;
    const int n0   = blockIdx.x * BN;
    const int m0   = blockIdx.y * BM;
    const int mw   = (wid >> 2) * 64;       // warp m offset
    const int nw   = (wid & 3) * 32;        // warp n offset

    const float* __restrict__ bias = z ? bcp : bcc;
    const __nv_bfloat16* __restrict__ pAh = g_Ah[z] + (size_t)m0 * DIM;
    const __nv_bfloat16* __restrict__ pAl = g_Al[z] + (size_t)m0 * DIM;
    const __nv_bfloat16* __restrict__ pBh = g_Wh[z] + (size_t)n0 * DIM;
    const __nv_bfloat16* __restrict__ pBl = g_Wl[z] + (size_t)n0 * DIM;

    if (tid < 32) {   // stage bias slice [n0, n0+128)
        float4 bv = *reinterpret_cast<const float4*>(&bias[n0 + tid * 4]);
        *reinterpret_cast<float4*>(sm + SM_BIAS + tid * 16) = bv;
    }

    // per-thread tile-copy coordinates: slot = row*4 + seg (2 slots/thread)
    const int rowT = tid >> 2;              // 0..63
    const int segT = tid & 3;               // 16B segment
    const uint32_t dOff0 = (uint32_t)(rowT * PITCH + segT * 16);
    const uint32_t dOff1 = dOff0 + 64 * PITCH;
    const size_t  sOff0 = (size_t)rowT * DIM + segT * 8;   // bf16 elements
    const size_t  sOff1 = sOff0 + (size_t)64 * DIM;

    // ldmatrix lane address offsets
    const uint32_t aRowOff =
        (uint32_t)((mw + (lane & 15)) * PITCH + ((lane >> 4) << 4));
    const uint32_t bRowOff =
        (uint32_t)((nw + ((lane >> 4) << 3) + (lane & 7)) * PITCH +
                   (((lane >> 3) & 1) << 4));

    float acc[4][4][4];
#pragma unroll
    for (int i = 0; i < 4; i++)
#pragma unroll
        for (int j = 0; j < 4; j++)
#pragma unroll
            for (int e = 0; e < 4; e++) acc[i][j][e] = 0.f;

    // ---- preload chunk 0 into stage 0
    {
        const uint32_t s0 = sbase;
        cp16(s0 + SM_AH + dOff0, pAh + sOff0);
        cp16(s0 + SM_AH + dOff1, pAh + sOff1);
        cp16(s0 + SM_AL + dOff0, pAl + sOff0);
        cp16(s0 + SM_AL + dOff1, pAl + sOff1);
        cp16(s0 + SM_BH + dOff0, pBh + sOff0);
        cp16(s0 + SM_BH + dOff1, pBh + sOff1);
        cp16(s0 + SM_BL + dOff0, pBl + sOff0);
        cp16(s0 + SM_BL + dOff1, pBl + sOff1);
        cp_commit();
    }
    cp_wait0();
    __syncthreads();

    for (int c = 0; c < NCHUNK; ++c) {
        const uint32_t cur = sbase + (uint32_t)((c & 1) * STAGE);
        // ---- issue next chunk's copies (overlap with compute below)
        if (c + 1 < NCHUNK) {
            const uint32_t nxt = sbase + (uint32_t)(((c + 1) & 1) * STAGE);
            const size_t ks = (size_t)(c + 1) * BK;
            cp16(nxt + SM_AH + dOff0, pAh + ks + sOff0);
            cp16(nxt + SM_AH + dOff1, pAh + ks + sOff1);
            cp16(nxt + SM_AL + dOff0, pAl + ks + sOff0);
            cp16(nxt + SM_AL + dOff1, pAl + ks + sOff1);
            cp16(nxt + SM_BH + dOff0, pBh + ks + sOff0);
            cp16(nxt + SM_BH + dOff1, pBh + ks + sOff1);
            cp16(nxt + SM_BL + dOff0, pBl + ks + sOff0);
            cp16(nxt + SM_BL + dOff1, pBl + ks + sOff1);
            cp_commit();
        }

        const uint32_t aH = cur + SM_AH + aRowOff;
        const uint32_t aL = cur + SM_AL + aRowOff;
        const uint32_t bH = cur + SM_BH + bRowOff;
        const uint32_t bL = cur + SM_BL + bRowOff;
#pragma unroll
        for (int ks = 0; ks < 2; ++ks) {
            const uint32_t ko = ks * 32;          // 16 bf16 = 32 B
            uint32_t ah[4][4], al4[4][4];
#pragma unroll
            for (int mt = 0; mt < 4; ++mt) ldsm_x4(ah[mt],  aH + mt * (16 * PITCH) + ko);
#pragma unroll
            for (int mt = 0; mt < 4; ++mt) ldsm_x4(al4[mt], aL + mt * (16 * PITCH) + ko);
#pragma unroll
            for (int j2 = 0; j2 < 2; ++j2) {
                uint32_t bh4[4], bl4[4];
                ldsm_x4(bh4, bH + j2 * (16 * PITCH) + ko);  // [N][K] == col-major KxN
                ldsm_x4(bl4, bL + j2 * (16 * PITCH) + ko);
#pragma unroll
                for (int mt = 0; mt < 4; ++mt) {
                    float* d0 = acc[mt][j2 * 2];
                    float* d1 = acc[mt][j2 * 2 + 1];
                    mma_bf16(d0, ah[mt],  bh4[0], bh4[1]);
                    mma_bf16(d1, ah[mt],  bh4[2], bh4[3]);
                    mma_bf16(d0, al4[mt], bh4[0], bh4[1]);
                    mma_bf16(d1, al4[mt], bh4[2], bh4[3]);
                    mma_bf16(d0, ah[mt],  bl4[0], bl4[1]);
                    mma_bf16(d1, ah[mt],  bl4[2], bl4[3]);
                }
            }
        }
        cp_wait0();
        __syncthreads();
    }

    // ---- epilogue: +bias, float2 stores
    float* C = out + (size_t)z * M_ROWS * DIM;
    const float* sb = reinterpret_cast<const float*>(sm + SM_BIAS);
#pragma unroll
    for (int mt = 0; mt < 4; ++mt) {
        const int r0 = m0 + mw + mt * 16 + (lane >> 2);
#pragma unroll
        for (int nt = 0; nt < 4; ++nt) {
            const int cl = nw + nt * 8 + (lane & 3) * 2;   // within [0,128)
            const float b0 = sb[cl], b1 = sb[cl + 1];
            float2 v0 = make_float2(acc[mt][nt][0] + b0, acc[mt][nt][1] + b1);
            float2 v1 = make_float2(acc[mt][nt][2] + b0, acc[mt][nt][3] + b1);
            *reinterpret_cast<float2*>(&C[(size_t)r0 * DIM + n0 + cl]) = v0;
            *reinterpret_cast<float2*>(&C[(size_t)(r0 + 8) * DIM + n0 + cl]) = v1;
        }
    }
}

// ------------------------------------------------------------------ launch
extern "C" void kernel_launch(void* const* d_in, const int* in_sizes, int n_in,
                              void* d_out, int out_size) {
    const float* atoms = (const float*)d_in[0];
    const float* amino = (const float*)d_in[1];
    const float* Wcc   = (const float*)d_in[15];
    const float* bcc   = (const float*)d_in[16];
    const float* Wcp   = (const float*)d_in[17];
    const float* bcp   = (const float*)d_in[18];
    float* out = (float*)d_out;

    static bool attr_set = false;
    if (!attr_set) {
        cudaFuncSetAttribute(biatt_gemm_kernel,
                             cudaFuncAttributeMaxDynamicSharedMemorySize, SM_TOT);
        attr_set = true;
    }

    fold_split_kernel<<<dim3(16, 16, 2), dim3(32, 32)>>>(Wcc, Wcp);
    split_A_kernel<<<dim3(M_ROWS * DIM / (256 * 4), 2), 256>>>(atoms, amino);

    dim3 grid(DIM / BN, M_ROWS / BM, 2);   // 4 x 48 x 2 = 384 CTAs
    biatt_gemm_kernel<<<grid, 256, SM_TOT>>>(bcc, bcp, out);
}

// round 7
// speedup vs baseline: 1.6569x; 1.6569x over previous
#include <cuda_runtime.h>
#include <cuda_bf16.h>
#include <cuda_fp16.h>
#include <cstdint>

// BiATT algebraic collapse: softmax over axis=1 of a [N,1] tensor == 1.0, so
// all four bi-attention branches are identity. cf = atoms @ (sum Wcc blocks) + bcc,
// pf = amino @ (sum Wcp blocks) + bcp  =>  two [6144x512]@[512x512] GEMMs.
// Single fp16 GEMM (fp32 accum); predicted rel_err ~ 2^-11.5 ~ 3.4e-4 < 1e-3.
// R7: fix R6 copy-loop bug (segments 1,3,5,7 of each row were never written).

#define DIM     512
#define M_ROWS  6144
#define BM      128
#define BN      128
#define BK      64
#define NCHUNK  (DIM / BK)     // 8

// preformed fp16 operands
__device__ __half g_W[2][DIM * DIM];      // folded, transposed [N][K]
__device__ __half g_A[2][M_ROWS * DIM];   // fp16 copy of activations

// ---- smem: rows of 64 fp16 (128 B) padded to 144 B; conflict-free ldmatrix
#define PITCH    144
#define TILEB    (BM * PITCH)            // 18432 per tile
#define STAGE    (2 * TILEB)             // A + B = 36864 per stage
#define SM_A     0
#define SM_B     TILEB
#define SM_BIAS  (2 * STAGE)             // 73728
#define SM_TOT   (SM_BIAS + 512)         // 74240 dynamic

// ---------------------------------------------------------------- helpers
__device__ __forceinline__ uint32_t smem_u32(const void* p) {
    return (uint32_t)__cvta_generic_to_shared(p);
}
__device__ __forceinline__ void cp16(uint32_t dst, const void* src) {
    asm volatile("cp.async.cg.shared.global [%0], [%1], 16;"
                 :: "r"(dst), "l"(src));
}
__device__ __forceinline__ void cp_commit() {
    asm volatile("cp.async.commit_group;");
}
__device__ __forceinline__ void cp_wait0() {
    asm volatile("cp.async.wait_group 0;");
}
__device__ __forceinline__ void ldsm_x4(uint32_t* r, uint32_t addr) {
    asm volatile("ldmatrix.sync.aligned.m8n8.x4.shared.b16 {%0,%1,%2,%3}, [%4];"
                 : "=r"(r[0]), "=r"(r[1]), "=r"(r[2]), "=r"(r[3]) : "r"(addr));
}
__device__ __forceinline__ void mma_f16(float* d, const uint32_t* a,
                                        uint32_t b0, uint32_t b1) {
    asm volatile(
        "mma.sync.aligned.m16n8k16.row.col.f32.f16.f16.f32 "
        "{%0,%1,%2,%3}, {%4,%5,%6,%7}, {%8,%9}, {%0,%1,%2,%3};"
        : "+f"(d[0]), "+f"(d[1]), "+f"(d[2]), "+f"(d[3])
        : "r"(a[0]), "r"(a[1]), "r"(a[2]), "r"(a[3]), "r"(b0), "r"(b1));
}

// ----------------------------------------------- prologue 1: fold + T W -> fp16
// g_W[z][n*512+k] = fp16( sum_b Wsrc[(b*512+k)*512+n] )
__global__ void fold_kernel(const float* __restrict__ Wcc,
                            const float* __restrict__ Wcp) {
    __shared__ float s[32][33];
    const int z = blockIdx.z;
    const float* __restrict__ W = z ? Wcp : Wcc;
    const int k = blockIdx.y * 32 + threadIdx.y;
    const int n = blockIdx.x * 32 + threadIdx.x;
    float v = 0.f;
#pragma unroll
    for (int b = 0; b < 4; b++) v += W[(size_t)(b * DIM + k) * DIM + n];
    s[threadIdx.y][threadIdx.x] = v;
    __syncthreads();
    const int n2 = blockIdx.x * 32 + threadIdx.y;
    const int k2 = blockIdx.y * 32 + threadIdx.x;
    g_W[z][(size_t)n2 * DIM + k2] = __float2half_rn(s[threadIdx.x][threadIdx.y]);
}

// ----------------------------------------------- prologue 2: A -> fp16
__global__ void __launch_bounds__(256)
convert_A_kernel(const float* __restrict__ atoms, const float* __restrict__ amino) {
    const int z = blockIdx.y;
    const float* __restrict__ X = z ? amino : atoms;
    const size_t idx = ((size_t)blockIdx.x * 256 + threadIdx.x) * 4;
    float4 v = *reinterpret_cast<const float4*>(&X[idx]);
    __half2 h0 = __floats2half2_rn(v.x, v.y);
    __half2 h1 = __floats2half2_rn(v.z, v.w);
    uint2 o = make_uint2(*reinterpret_cast<uint32_t*>(&h0),
                         *reinterpret_cast<uint32_t*>(&h1));
    *reinterpret_cast<uint2*>(&g_A[z][idx]) = o;
}

// --------------------------------------------------- HMMA GEMM + bias
// grid (4, 48, 2), 256 threads; warp tile 64x32 (2x4 warp grid); 2-stage pipe
__global__ void __launch_bounds__(256, 2)
biatt_gemm_kernel(const float* __restrict__ bcc,
                  const float* __restrict__ bcp,
                  float* __restrict__ out) {
    extern __shared__ __align__(16) char sm[];
    const uint32_t sbase = smem_u32(sm);

    const int tid  = threadIdx.x;
    const int wid  = tid >> 5;
    const int lane = tid & 31;
    const int z    = blockIdx.z;
    const int n0   = blockIdx.x * BN;
    const int m0   = blockIdx.y * BM;
    const int mw   = (wid >> 2) * 64;       // warp m offset
    const int nw   = (wid & 3) * 32;        // warp n offset

    const float* __restrict__ bias = z ? bcp : bcc;
    const __half* __restrict__ pA = g_A[z] + (size_t)m0 * DIM;
    const __half* __restrict__ pB = g_W[z] + (size_t)n0 * DIM;

    if (tid < 32) {   // stage bias slice [n0, n0+128)
        float4 bv = *reinterpret_cast<const float4*>(&bias[n0 + tid * 4]);
        *reinterpret_cast<float4*>(sm + SM_BIAS + tid * 16) = bv;
    }

    // per-thread copy slots: tile = 128 rows x 8 x 16B segs; 4 contiguous segs
    const int rowT = tid >> 1;              // 0..127
    const int segT = (tid & 1) * 4;         // first 16B segment (0 or 4)
    const uint32_t dOffA = (uint32_t)(rowT * PITCH + segT * 16);
    const size_t   sOffA = (size_t)rowT * DIM + segT * 8;   // fp16 elems

    // ldmatrix lane address offsets
    const uint32_t aRowOff =
        (uint32_t)((mw + (lane & 15)) * PITCH + ((lane >> 4) << 4));
    const uint32_t bRowOff =
        (uint32_t)((nw + ((lane >> 4) << 3) + (lane & 7)) * PITCH +
                   (((lane >> 3) & 1) << 4));

    float acc[4][4][4];
#pragma unroll
    for (int i = 0; i < 4; i++)
#pragma unroll
        for (int j = 0; j < 4; j++)
#pragma unroll
            for (int e = 0; e < 4; e++) acc[i][j][e] = 0.f;

    // ---- preload chunk 0 into stage 0 (4 contiguous 16B segs per tile)
    {
#pragma unroll
        for (int s = 0; s < 4; ++s) {
            cp16(sbase + SM_A + dOffA + s * 16, pA + sOffA + s * 8);
            cp16(sbase + SM_B + dOffA + s * 16, pB + sOffA + s * 8);
        }
        cp_commit();
    }
    cp_wait0();
    __syncthreads();

    for (int c = 0; c < NCHUNK; ++c) {
        const uint32_t cur = sbase + (uint32_t)((c & 1) * STAGE);
        // ---- issue next chunk's copies (overlap with compute below)
        if (c + 1 < NCHUNK) {
            const uint32_t nxt = sbase + (uint32_t)(((c + 1) & 1) * STAGE);
            const size_t ks = (size_t)(c + 1) * BK;
#pragma unroll
            for (int s = 0; s < 4; ++s) {
                cp16(nxt + SM_A + dOffA + s * 16, pA + ks + sOffA + s * 8);
                cp16(nxt + SM_B + dOffA + s * 16, pB + ks + sOffA + s * 8);
            }
            cp_commit();
        }

        const uint32_t aP = cur + SM_A + aRowOff;
        const uint32_t bP = cur + SM_B + bRowOff;
#pragma unroll
        for (int ks = 0; ks < 4; ++ks) {
            const uint32_t ko = ks * 32;          // 16 fp16 = 32 B
            uint32_t af[4][4];
#pragma unroll
            for (int mt = 0; mt < 4; ++mt)
                ldsm_x4(af[mt], aP + mt * (16 * PITCH) + ko);
#pragma unroll
            for (int j2 = 0; j2 < 2; ++j2) {
                uint32_t bf[4];
                ldsm_x4(bf, bP + j2 * (16 * PITCH) + ko);  // [N][K] == col-major KxN
#pragma unroll
                for (int mt = 0; mt < 4; ++mt) {
                    mma_f16(acc[mt][j2 * 2],     af[mt], bf[0], bf[1]);
                    mma_f16(acc[mt][j2 * 2 + 1], af[mt], bf[2], bf[3]);
                }
            }
        }
        cp_wait0();
        __syncthreads();
    }

    // ---- epilogue: +bias, float2 stores
    float* C = out + (size_t)z * M_ROWS * DIM;
    const float* sb = reinterpret_cast<const float*>(sm + SM_BIAS);
#pragma unroll
    for (int mt = 0; mt < 4; ++mt) {
        const int r0 = m0 + mw + mt * 16 + (lane >> 2);
#pragma unroll
        for (int nt = 0; nt < 4; ++nt) {
            const int cl = nw + nt * 8 + (lane & 3) * 2;   // within [0,128)
            const float b0 = sb[cl], b1 = sb[cl + 1];
            float2 v0 = make_float2(acc[mt][nt][0] + b0, acc[mt][nt][1] + b1);
            float2 v1 = make_float2(acc[mt][nt][2] + b0, acc[mt][nt][3] + b1);
            *reinterpret_cast<float2*>(&C[(size_t)r0 * DIM + n0 + cl]) = v0;
            *reinterpret_cast<float2*>(&C[(size_t)(r0 + 8) * DIM + n0 + cl]) = v1;
        }
    }
}

// ------------------------------------------------------------------ launch
extern "C" void kernel_launch(void* const* d_in, const int* in_sizes, int n_in,
                              void* d_out, int out_size) {
    const float* atoms = (const float*)d_in[0];
    const float* amino = (const float*)d_in[1];
    const float* Wcc   = (const float*)d_in[15];
    const float* bcc   = (const float*)d_in[16];
    const float* Wcp   = (const float*)d_in[17];
    const float* bcp   = (const float*)d_in[18];
    float* out = (float*)d_out;

    static bool attr_set = false;
    if (!attr_set) {
        cudaFuncSetAttribute(biatt_gemm_kernel,
                             cudaFuncAttributeMaxDynamicSharedMemorySize, SM_TOT);
        attr_set = true;
    }

    fold_kernel<<<dim3(16, 16, 2), dim3(32, 32)>>>(Wcc, Wcp);
    convert_A_kernel<<<dim3(M_ROWS * DIM / (256 * 4), 2), 256>>>(atoms, amino);

    dim3 grid(DIM / BN, M_ROWS / BM, 2);   // 4 x 48 x 2 = 384 CTAs
    biatt_gemm_kernel<<<grid, 256, SM_TOT>>>(bcc, bcp, out);
}

// round 8
// speedup vs baseline: 1.7459x; 1.0538x over previous
#include <cuda_runtime.h>
#include <cuda_bf16.h>
#include <cuda_fp16.h>
#include <cstdint>

// BiATT algebraic collapse: softmax over axis=1 of a [N,1] tensor == 1.0, so
// all four bi-attention branches are identity. cf = atoms @ (sum Wcc blocks) + bcc,
// pf = amino @ (sum Wcp blocks) + bcp  =>  two [6144x512]@[512x512] GEMMs.
// Single fp16 GEMM (fp32 accum), rel_err ~3e-4 (measured 2.93e-4 in R7).
// R8: 3-stage cp.async pipeline; MLP fixes in both prologue kernels.

#define DIM     512
#define M_ROWS  6144
#define BM      128
#define BN      128
#define BK      64
#define NCHUNK  (DIM / BK)     // 8
#define NSTAGE  3

// preformed fp16 operands
__device__ __half g_W[2][DIM * DIM];      // folded, transposed [N][K]
__device__ __half g_A[2][M_ROWS * DIM];   // fp16 copy of activations

// ---- smem: rows of 64 fp16 (128 B) padded to 144 B; conflict-free ldmatrix
#define PITCH    144
#define TILEB    (BM * PITCH)            // 18432 per tile
#define STAGE    (2 * TILEB)             // A + B = 36864 per stage
#define SM_A     0
#define SM_B     TILEB
#define SM_BIAS  (NSTAGE * STAGE)        // 110592
#define SM_TOT   (SM_BIAS + 512)         // 111104 dynamic (occ 2: 217KB/SM)

// ---------------------------------------------------------------- helpers
__device__ __forceinline__ uint32_t smem_u32(const void* p) {
    return (uint32_t)__cvta_generic_to_shared(p);
}
__device__ __forceinline__ void cp16(uint32_t dst, const void* src) {
    asm volatile("cp.async.cg.shared.global [%0], [%1], 16;"
                 :: "r"(dst), "l"(src));
}
__device__ __forceinline__ void cp_commit() {
    asm volatile("cp.async.commit_group;");
}
__device__ __forceinline__ void cp_wait1() {
    asm volatile("cp.async.wait_group 1;");
}
__device__ __forceinline__ void ldsm_x4(uint32_t* r, uint32_t addr) {
    asm volatile("ldmatrix.sync.aligned.m8n8.x4.shared.b16 {%0,%1,%2,%3}, [%4];"
                 : "=r"(r[0]), "=r"(r[1]), "=r"(r[2]), "=r"(r[3]) : "r"(addr));
}
__device__ __forceinline__ void mma_f16(float* d, const uint32_t* a,
                                        uint32_t b0, uint32_t b1) {
    asm volatile(
        "mma.sync.aligned.m16n8k16.row.col.f32.f16.f16.f32 "
        "{%0,%1,%2,%3}, {%4,%5,%6,%7}, {%8,%9}, {%0,%1,%2,%3};"
        : "+f"(d[0]), "+f"(d[1]), "+f"(d[2]), "+f"(d[3])
        : "r"(a[0]), "r"(a[1]), "r"(a[2]), "r"(a[3]), "r"(b0), "r"(b1));
}

// ----------------------------------------------- prologue 1: fold + T W -> fp16
// g_W[z][n*512+k] = fp16( sum_b Wsrc[(b*512+k)*512+n] );  MLP=16 per thread
__global__ void fold_kernel(const float* __restrict__ Wcc,
                            const float* __restrict__ Wcp) {
    __shared__ float s[32][33];
    const int z = blockIdx.z;
    const float* __restrict__ W = z ? Wcp : Wcc;
    const int k0 = blockIdx.y * 32;
    const int n0 = blockIdx.x * 32;
    const int tx = threadIdx.x;        // 0..31
    const int ty = threadIdx.y;        // 0..7
    float v[4] = {0.f, 0.f, 0.f, 0.f};
#pragma unroll
    for (int b = 0; b < 4; b++) {
#pragma unroll
        for (int i = 0; i < 4; i++) {
            const int k = k0 + ty + i * 8;
            v[i] += W[(size_t)(b * DIM + k) * DIM + n0 + tx];
        }
    }
#pragma unroll
    for (int i = 0; i < 4; i++) s[tx][ty + i * 8] = v[i];
    __syncthreads();
#pragma unroll
    for (int i = 0; i < 4; i++) {
        const int n2 = n0 + ty + i * 8;
        const int k2 = k0 + tx;
        g_W[z][(size_t)n2 * DIM + k2] = __float2half_rn(s[ty + i * 8][tx]);
    }
}

// ----------------------------------------------- prologue 2: A -> fp16, MLP=4
__global__ void __launch_bounds__(256)
convert_A_kernel(const float* __restrict__ atoms, const float* __restrict__ amino) {
    const int z = blockIdx.y;
    const float* __restrict__ X = z ? amino : atoms;
    const size_t base = ((size_t)blockIdx.x * 1024 + threadIdx.x) * 4;
    float4 v[4];
#pragma unroll
    for (int i = 0; i < 4; i++)
        v[i] = *reinterpret_cast<const float4*>(&X[base + (size_t)i * 1024]);
#pragma unroll
    for (int i = 0; i < 4; i++) {
        __half2 h0 = __floats2half2_rn(v[i].x, v[i].y);
        __half2 h1 = __floats2half2_rn(v[i].z, v[i].w);
        uint2 o = make_uint2(*reinterpret_cast<uint32_t*>(&h0),
                             *reinterpret_cast<uint32_t*>(&h1));
        *reinterpret_cast<uint2*>(&g_A[z][base + (size_t)i * 1024]) = o;
    }
}

// --------------------------------------------------- HMMA GEMM + bias
// grid (4, 48, 2), 256 threads; warp tile 64x32 (2x4 warp grid); 3-stage pipe
__global__ void __launch_bounds__(256, 2)
biatt_gemm_kernel(const float* __restrict__ bcc,
                  const float* __restrict__ bcp,
                  float* __restrict__ out) {
    extern __shared__ __align__(16) char sm[];
    const uint32_t sbase = smem_u32(sm);

    const int tid  = threadIdx.x;
    const int wid  = tid >> 5;
    const int lane = tid & 31;
    const int z    = blockIdx.z;
    const int n0   = blockIdx.x * BN;
    const int m0   = blockIdx.y * BM;
    const int mw   = (wid >> 2) * 64;       // warp m offset
    const int nw   = (wid & 3) * 32;        // warp n offset

    const float* __restrict__ bias = z ? bcp : bcc;
    const __half* __restrict__ pA = g_A[z] + (size_t)m0 * DIM;
    const __half* __restrict__ pB = g_W[z] + (size_t)n0 * DIM;

    if (tid < 32) {   // stage bias slice [n0, n0+128)
        float4 bv = *reinterpret_cast<const float4*>(&bias[n0 + tid * 4]);
        *reinterpret_cast<float4*>(sm + SM_BIAS + tid * 16) = bv;
    }

    // per-thread copy slots: tile = 128 rows x 8 x 16B segs; 4 contiguous segs
    const int rowT = tid >> 1;              // 0..127
    const int segT = (tid & 1) * 4;         // first 16B segment (0 or 4)
    const uint32_t dOffA = (uint32_t)(rowT * PITCH + segT * 16);
    const size_t   sOffA = (size_t)rowT * DIM + segT * 8;   // fp16 elems

    // ldmatrix lane address offsets
    const uint32_t aRowOff =
        (uint32_t)((mw + (lane & 15)) * PITCH + ((lane >> 4) << 4));
    const uint32_t bRowOff =
        (uint32_t)((nw + ((lane >> 4) << 3) + (lane & 7)) * PITCH +
                   (((lane >> 3) & 1) << 4));

    float acc[4][4][4];
#pragma unroll
    for (int i = 0; i < 4; i++)
#pragma unroll
        for (int j = 0; j < 4; j++)
#pragma unroll
            for (int e = 0; e < 4; e++) acc[i][j][e] = 0.f;

    // ---- preload chunks 0 and 1 into stages 0 and 1
#pragma unroll
    for (int p = 0; p < 2; ++p) {
        const uint32_t st = sbase + (uint32_t)(p * STAGE);
        const size_t ks = (size_t)p * BK;
#pragma unroll
        for (int s = 0; s < 4; ++s) {
            cp16(st + SM_A + dOffA + s * 16, pA + ks + sOffA + s * 8);
            cp16(st + SM_B + dOffA + s * 16, pB + ks + sOffA + s * 8);
        }
        cp_commit();
    }

    int stage = 0;
    for (int c = 0; c < NCHUNK; ++c) {
        cp_wait1();            // chunk c's group complete (c+1's may fly)
        __syncthreads();       // stage (c+2)%3 free (compute c-1 done everywhere)

        // ---- issue chunk c+2 copies into the freed stage
        if (c + 2 < NCHUNK) {
            const int nstage = (stage + 2 >= NSTAGE) ? stage + 2 - NSTAGE : stage + 2;
            const uint32_t nxt = sbase + (uint32_t)(nstage * STAGE);
            const size_t ks = (size_t)(c + 2) * BK;
#pragma unroll
            for (int s = 0; s < 4; ++s) {
                cp16(nxt + SM_A + dOffA + s * 16, pA + ks + sOffA + s * 8);
                cp16(nxt + SM_B + dOffA + s * 16, pB + ks + sOffA + s * 8);
            }
            cp_commit();
        } else {
            cp_commit();       // keep group counts uniform for wait_group 1
        }

        const uint32_t cur = sbase + (uint32_t)(stage * STAGE);
        const uint32_t aP = cur + SM_A + aRowOff;
        const uint32_t bP = cur + SM_B + bRowOff;
#pragma unroll
        for (int ks = 0; ks < 4; ++ks) {
            const uint32_t ko = ks * 32;          // 16 fp16 = 32 B
            uint32_t af[4][4];
#pragma unroll
            for (int mt = 0; mt < 4; ++mt)
                ldsm_x4(af[mt], aP + mt * (16 * PITCH) + ko);
#pragma unroll
            for (int j2 = 0; j2 < 2; ++j2) {
                uint32_t bf[4];
                ldsm_x4(bf, bP + j2 * (16 * PITCH) + ko);  // [N][K] == col-major KxN
#pragma unroll
                for (int mt = 0; mt < 4; ++mt) {
                    mma_f16(acc[mt][j2 * 2],     af[mt], bf[0], bf[1]);
                    mma_f16(acc[mt][j2 * 2 + 1], af[mt], bf[2], bf[3]);
                }
            }
        }
        stage = (stage + 1 >= NSTAGE) ? 0 : stage + 1;
    }

    // ---- epilogue: +bias, float2 stores
    float* C = out + (size_t)z * M_ROWS * DIM;
    const float* sb = reinterpret_cast<const float*>(sm + SM_BIAS);
#pragma unroll
    for (int mt = 0; mt < 4; ++mt) {
        const int r0 = m0 + mw + mt * 16 + (lane >> 2);
#pragma unroll
        for (int nt = 0; nt < 4; ++nt) {
            const int cl = nw + nt * 8 + (lane & 3) * 2;   // within [0,128)
            const float b0 = sb[cl], b1 = sb[cl + 1];
            float2 v0 = make_float2(acc[mt][nt][0] + b0, acc[mt][nt][1] + b1);
            float2 v1 = make_float2(acc[mt][nt][2] + b0, acc[mt][nt][3] + b1);
            *reinterpret_cast<float2*>(&C[(size_t)r0 * DIM + n0 + cl]) = v0;
            *reinterpret_cast<float2*>(&C[(size_t)(r0 + 8) * DIM + n0 + cl]) = v1;
        }
    }
}

// ------------------------------------------------------------------ launch
extern "C" void kernel_launch(void* const* d_in, const int* in_sizes, int n_in,
                              void* d_out, int out_size) {
    const float* atoms = (const float*)d_in[0];
    const float* amino = (const float*)d_in[1];
    const float* Wcc   = (const float*)d_in[15];
    const float* bcc   = (const float*)d_in[16];
    const float* Wcp   = (const float*)d_in[17];
    const float* bcp   = (const float*)d_in[18];
    float* out = (float*)d_out;

    static bool attr_set = false;
    if (!attr_set) {
        cudaFuncSetAttribute(biatt_gemm_kernel,
                             cudaFuncAttributeMaxDynamicSharedMemorySize, SM_TOT);
        attr_set = true;
    }

    fold_kernel<<<dim3(16, 16, 2), dim3(32, 8)>>>(Wcc, Wcp);
    convert_A_kernel<<<dim3(M_ROWS * DIM / (1024 * 4), 2), 256>>>(atoms, amino);

    dim3 grid(DIM / BN, M_ROWS / BM, 2);   // 4 x 48 x 2 = 384 CTAs
    biatt_gemm_kernel<<<grid, 256, SM_TOT>>>(bcc, bcp, out);
}

// round 9
// speedup vs baseline: 1.7628x; 1.0097x over previous
#include <cuda_runtime.h>
#include <cuda_bf16.h>
#include <cuda_fp16.h>
#include <cstdint>

// BiATT algebraic collapse: softmax over axis=1 of a [N,1] tensor == 1.0, so
// all four bi-attention branches are identity. cf = atoms @ (sum Wcc blocks) + bcc,
// pf = amino @ (sum Wcp blocks) + bcp  =>  two [6144x512]@[512x512] GEMMs.
// Single fp16 GEMM (fp32 accum), rel_err 2.93e-4 (measured R7/R8).
// R9: fold-W and convert-A fused into ONE prep kernel (concurrent blocks);
// GEMM identical to R8 (3-stage cp.async, 384 CTAs @ occ 2).

#define DIM     512
#define M_ROWS  6144
#define BM      128
#define BN      128
#define BK      64
#define NCHUNK  (DIM / BK)     // 8
#define NSTAGE  3

// preformed fp16 operands
__device__ __half g_W[2][DIM * DIM];      // folded, transposed [N][K]
__device__ __half g_A[2][M_ROWS * DIM];   // fp16 copy of activations

// ---- smem: rows of 64 fp16 (128 B) padded to 144 B; conflict-free ldmatrix
#define PITCH    144
#define TILEB    (BM * PITCH)            // 18432 per tile
#define STAGE    (2 * TILEB)             // A + B = 36864 per stage
#define SM_A     0
#define SM_B     TILEB
#define SM_BIAS  (NSTAGE * STAGE)        // 110592
#define SM_TOT   (SM_BIAS + 512)         // 111104 dynamic (occ 2)

// ---------------------------------------------------------------- helpers
__device__ __forceinline__ uint32_t smem_u32(const void* p) {
    return (uint32_t)__cvta_generic_to_shared(p);
}
__device__ __forceinline__ void cp16(uint32_t dst, const void* src) {
    asm volatile("cp.async.cg.shared.global [%0], [%1], 16;"
                 :: "r"(dst), "l"(src));
}
__device__ __forceinline__ void cp_commit() {
    asm volatile("cp.async.commit_group;");
}
__device__ __forceinline__ void cp_wait1() {
    asm volatile("cp.async.wait_group 1;");
}
__device__ __forceinline__ void ldsm_x4(uint32_t* r, uint32_t addr) {
    asm volatile("ldmatrix.sync.aligned.m8n8.x4.shared.b16 {%0,%1,%2,%3}, [%4];"
                 : "=r"(r[0]), "=r"(r[1]), "=r"(r[2]), "=r"(r[3]) : "r"(addr));
}
__device__ __forceinline__ void mma_f16(float* d, const uint32_t* a,
                                        uint32_t b0, uint32_t b1) {
    asm volatile(
        "mma.sync.aligned.m16n8k16.row.col.f32.f16.f16.f32 "
        "{%0,%1,%2,%3}, {%4,%5,%6,%7}, {%8,%9}, {%0,%1,%2,%3};"
        : "+f"(d[0]), "+f"(d[1]), "+f"(d[2]), "+f"(d[3])
        : "r"(a[0]), "r"(a[1]), "r"(a[2]), "r"(a[3]), "r"(b0), "r"(b1));
}

// ---------------------------- fused prologue: fold-W (transpose) + convert-A
// grid: (256 + 384, 2), block: 256 threads.
//   blockIdx.x <  256 : fold  — g_W[z][n*512+k] = fp16(sum_b W[(b*512+k)*512+n])
//   blockIdx.x >= 256 : convert — g_A[z] = fp16(X)
__global__ void __launch_bounds__(256)
prep_kernel(const float* __restrict__ atoms, const float* __restrict__ amino,
            const float* __restrict__ Wcc,   const float* __restrict__ Wcp) {
    const int z   = blockIdx.y;
    const int tid = threadIdx.x;

    if (blockIdx.x < 256) {
        // ---- fold: 32n x 32k tile per block (16 x 16 blocks per z)
        __shared__ float s[32][33];
        const float* __restrict__ W = z ? Wcp : Wcc;
        const int nb = blockIdx.x & 15;
        const int kb = blockIdx.x >> 4;
        const int n0 = nb * 32;
        const int k0 = kb * 32;
        const int tx = tid & 31;        // n lane
        const int ty = tid >> 5;        // k lane base (0..7)
        float v[4] = {0.f, 0.f, 0.f, 0.f};
#pragma unroll
        for (int b = 0; b < 4; b++) {
#pragma unroll
            for (int i = 0; i < 4; i++) {
                const int k = k0 + ty + i * 8;
                v[i] += W[(size_t)(b * DIM + k) * DIM + n0 + tx];
            }
        }
#pragma unroll
        for (int i = 0; i < 4; i++) s[tx][ty + i * 8] = v[i];
        __syncthreads();
#pragma unroll
        for (int i = 0; i < 4; i++) {
            const int n2 = n0 + ty + i * 8;
            const int k2 = k0 + tx;
            g_W[z][(size_t)n2 * DIM + k2] = __float2half_rn(s[ty + i * 8][tx]);
        }
    } else {
        // ---- convert: 2048 float4s per block (384 blocks per z), MLP=8
        const float* __restrict__ X = z ? amino : atoms;
        const size_t base = ((size_t)(blockIdx.x - 256) * 2048 + tid) * 4;
        float4 v[8];
#pragma unroll
        for (int i = 0; i < 8; i++)
            v[i] = *reinterpret_cast<const float4*>(&X[base + (size_t)i * 1024]);
#pragma unroll
        for (int i = 0; i < 8; i++) {
            __half2 h0 = __floats2half2_rn(v[i].x, v[i].y);
            __half2 h1 = __floats2half2_rn(v[i].z, v[i].w);
            uint2 o = make_uint2(*reinterpret_cast<uint32_t*>(&h0),
                                 *reinterpret_cast<uint32_t*>(&h1));
            *reinterpret_cast<uint2*>(&g_A[z][base + (size_t)i * 1024]) = o;
        }
    }
}

// --------------------------------------------------- HMMA GEMM + bias
// grid (4, 48, 2), 256 threads; warp tile 64x32 (2x4 warp grid); 3-stage pipe
__global__ void __launch_bounds__(256, 2)
biatt_gemm_kernel(const float* __restrict__ bcc,
                  const float* __restrict__ bcp,
                  float* __restrict__ out) {
    extern __shared__ __align__(16) char sm[];
    const uint32_t sbase = smem_u32(sm);

    const int tid  = threadIdx.x;
    const int wid  = tid >> 5;
    const int lane = tid & 31;
    const int z    = blockIdx.z;
    const int n0   = blockIdx.x * BN;
    const int m0   = blockIdx.y * BM;
    const int mw   = (wid >> 2) * 64;       // warp m offset
    const int nw   = (wid & 3) * 32;        // warp n offset

    const float* __restrict__ bias = z ? bcp : bcc;
    const __half* __restrict__ pA = g_A[z] + (size_t)m0 * DIM;
    const __half* __restrict__ pB = g_W[z] + (size_t)n0 * DIM;

    if (tid < 32) {   // stage bias slice [n0, n0+128)
        float4 bv = *reinterpret_cast<const float4*>(&bias[n0 + tid * 4]);
        *reinterpret_cast<float4*>(sm + SM_BIAS + tid * 16) = bv;
    }

    // per-thread copy slots: tile = 128 rows x 8 x 16B segs; 4 contiguous segs
    const int rowT = tid >> 1;              // 0..127
    const int segT = (tid & 1) * 4;         // first 16B segment (0 or 4)
    const uint32_t dOffA = (uint32_t)(rowT * PITCH + segT * 16);
    const size_t   sOffA = (size_t)rowT * DIM + segT * 8;   // fp16 elems

    // ldmatrix lane address offsets
    const uint32_t aRowOff =
        (uint32_t)((mw + (lane & 15)) * PITCH + ((lane >> 4) << 4));
    const uint32_t bRowOff =
        (uint32_t)((nw + ((lane >> 4) << 3) + (lane & 7)) * PITCH +
                   (((lane >> 3) & 1) << 4));

    float acc[4][4][4];
#pragma unroll
    for (int i = 0; i < 4; i++)
#pragma unroll
        for (int j = 0; j < 4; j++)
#pragma unroll
            for (int e = 0; e < 4; e++) acc[i][j][e] = 0.f;

    // ---- preload chunks 0 and 1 into stages 0 and 1
#pragma unroll
    for (int p = 0; p < 2; ++p) {
        const uint32_t st = sbase + (uint32_t)(p * STAGE);
        const size_t ks = (size_t)p * BK;
#pragma unroll
        for (int s = 0; s < 4; ++s) {
            cp16(st + SM_A + dOffA + s * 16, pA + ks + sOffA + s * 8);
            cp16(st + SM_B + dOffA + s * 16, pB + ks + sOffA + s * 8);
        }
        cp_commit();
    }

    int stage = 0;
    for (int c = 0; c < NCHUNK; ++c) {
        cp_wait1();            // chunk c's group complete (c+1's may fly)
        __syncthreads();       // stage (c+2)%3 free (compute c-1 done everywhere)

        // ---- issue chunk c+2 copies into the freed stage
        if (c + 2 < NCHUNK) {
            const int nstage = (stage + 2 >= NSTAGE) ? stage + 2 - NSTAGE : stage + 2;
            const uint32_t nxt = sbase + (uint32_t)(nstage * STAGE);
            const size_t ks = (size_t)(c + 2) * BK;
#pragma unroll
            for (int s = 0; s < 4; ++s) {
                cp16(nxt + SM_A + dOffA + s * 16, pA + ks + sOffA + s * 8);
                cp16(nxt + SM_B + dOffA + s * 16, pB + ks + sOffA + s * 8);
            }
            cp_commit();
        } else {
            cp_commit();       // keep group counts uniform for wait_group 1
        }

        const uint32_t cur = sbase + (uint32_t)(stage * STAGE);
        const uint32_t aP = cur + SM_A + aRowOff;
        const uint32_t bP = cur + SM_B + bRowOff;
#pragma unroll
        for (int ks = 0; ks < 4; ++ks) {
            const uint32_t ko = ks * 32;          // 16 fp16 = 32 B
            uint32_t af[4][4];
#pragma unroll
            for (int mt = 0; mt < 4; ++mt)
                ldsm_x4(af[mt], aP + mt * (16 * PITCH) + ko);
#pragma unroll
            for (int j2 = 0; j2 < 2; ++j2) {
                uint32_t bf[4];
                ldsm_x4(bf, bP + j2 * (16 * PITCH) + ko);  // [N][K] == col-major KxN
#pragma unroll
                for (int mt = 0; mt < 4; ++mt) {
                    mma_f16(acc[mt][j2 * 2],     af[mt], bf[0], bf[1]);
                    mma_f16(acc[mt][j2 * 2 + 1], af[mt], bf[2], bf[3]);
                }
            }
        }
        stage = (stage + 1 >= NSTAGE) ? 0 : stage + 1;
    }

    // ---- epilogue: +bias, float2 stores
    float* C = out + (size_t)z * M_ROWS * DIM;
    const float* sb = reinterpret_cast<const float*>(sm + SM_BIAS);
#pragma unroll
    for (int mt = 0; mt < 4; ++mt) {
        const int r0 = m0 + mw + mt * 16 + (lane >> 2);
#pragma unroll
        for (int nt = 0; nt < 4; ++nt) {
            const int cl = nw + nt * 8 + (lane & 3) * 2;   // within [0,128)
            const float b0 = sb[cl], b1 = sb[cl + 1];
            float2 v0 = make_float2(acc[mt][nt][0] + b0, acc[mt][nt][1] + b1);
            float2 v1 = make_float2(acc[mt][nt][2] + b0, acc[mt][nt][3] + b1);
            *reinterpret_cast<float2*>(&C[(size_t)r0 * DIM + n0 + cl]) = v0;
            *reinterpret_cast<float2*>(&C[(size_t)(r0 + 8) * DIM + n0 + cl]) = v1;
        }
    }
}

// ------------------------------------------------------------------ launch
extern "C" void kernel_launch(void* const* d_in, const int* in_sizes, int n_in,
                              void* d_out, int out_size) {
    const float* atoms = (const float*)d_in[0];
    const float* amino = (const float*)d_in[1];
    const float* Wcc   = (const float*)d_in[15];
    const float* bcc   = (const float*)d_in[16];
    const float* Wcp   = (const float*)d_in[17];
    const float* bcp   = (const float*)d_in[18];
    float* out = (float*)d_out;

    static bool attr_set = false;
    if (!attr_set) {
        cudaFuncSetAttribute(biatt_gemm_kernel,
                             cudaFuncAttributeMaxDynamicSharedMemorySize, SM_TOT);
        attr_set = true;
    }

    prep_kernel<<<dim3(256 + 384, 2), 256>>>(atoms, amino, Wcc, Wcp);

    dim3 grid(DIM / BN, M_ROWS / BM, 2);   // 4 x 48 x 2 = 384 CTAs
    biatt_gemm_kernel<<<grid, 256, SM_TOT>>>(bcc, bcp, out);
}